// round 7
// baseline (speedup 1.0000x reference)
#include <cuda_runtime.h>

#define BATCH 128
#define DIM   65536
#define NELEM (BATCH * DIM)

typedef unsigned long long u64;

// ---- scratch / precomputed tables (static device memory; no runtime allocs) ----
static __device__ float2 g_bufA[NELEM];          // 64 MB
static __device__ float2 g_bufB[NELEM];          // 64 MB
static __device__ float  g_partials[BATCH * 16];
static __device__ float2 g_cs[3][16];            // (cos(th/2), sin(th/2)) per layer/wire
static __device__ float2 g_Dhi[3][256];          // diagonal phase, wires 0..7  (bits 15..8)
static __device__ float2 g_Dlo[3][256];          // diagonal phase, wires 8..15 (bits 7..0)
static __device__ float  g_Ghi[256];             // head-weighted Z signs, wires 0..7
static __device__ float  g_Glo[256];             // head-weighted Z signs, wires 8..15

// ---- packed f32x2 helpers (FFMA2 path: PTX-only) ----
__device__ __forceinline__ u64 pk(float x, float y) {
    u64 r; asm("mov.b64 %0,{%1,%2};" : "=l"(r) : "f"(x), "f"(y)); return r;
}
__device__ __forceinline__ void upk(u64 a, float& x, float& y) {
    asm("mov.b64 {%0,%1},%2;" : "=f"(x), "=f"(y) : "l"(a));
}
__device__ __forceinline__ u64 fma2(u64 a, u64 b, u64 c) {
    u64 r; asm("fma.rn.f32x2 %0,%1,%2,%3;" : "=l"(r) : "l"(a), "l"(b), "l"(c)); return r;
}
__device__ __forceinline__ u64 mul2(u64 a, u64 b) {
    u64 r; asm("mul.rn.f32x2 %0,%1,%2;" : "=l"(r) : "l"(a), "l"(b)); return r;
}

// swizzles
__device__ __forceinline__ int swz(int i) {      // for k_low_real patterns
    return i ^ ((i >> 4) & 15) ^ (((i >> 8) & 1) << 4);
}
__device__ __forceinline__ int sw2(int i) {      // for fuse-kernel staged tile
    return i ^ ((i >> 4) & 15);
}

// Composite CNOT-ring permutation (forward basis map): out[M(a)] = psi[a].
__device__ __forceinline__ int permM(int a) {
    int t = a;
    t ^= t >> 8; t ^= t >> 4; t ^= t >> 2; t ^= t >> 1;
    return t ^ ((t & 1) << 15);
}
__device__ __forceinline__ int sfx4(int m) { m ^= m >> 2; m ^= m >> 1; return m & 15; }

// 4 RY butterflies; local bit q of j <-> wire (wtop - q).
__device__ __forceinline__ void bfly4_real(float v[16], int layer, int wtop) {
#pragma unroll
    for (int q = 0; q < 4; q++) {
        float2 cs = g_cs[layer][wtop - q];
        float c = cs.x, s = cs.y;
#pragma unroll
        for (int j = 0; j < 16; j++) {
            if (!(j & (1 << q))) {
                int j1 = j | (1 << q);
                float x0 = v[j], x1 = v[j1];
                v[j]  = c * x0 - s * x1;
                v[j1] = s * x0 + c * x1;
            }
        }
    }
}

__device__ __forceinline__ void bfly4_pk(u64 v[16], int layer, int wtop) {
#pragma unroll
    for (int q = 0; q < 4; q++) {
        float2 cs = g_cs[layer][wtop - q];
        u64 cc = pk(cs.x, cs.x), sp = pk(cs.y, cs.y), sn = pk(-cs.y, -cs.y);
#pragma unroll
        for (int j = 0; j < 16; j++) {
            if (!(j & (1 << q))) {
                int j1 = j | (1 << q);
                u64 x0 = v[j], x1 = v[j1];
                v[j]  = fma2(sn, x1, mul2(cc, x0));
                v[j1] = fma2(sp, x0, mul2(cc, x1));
            }
        }
    }
}

// ---- precompute tables ----
__global__ void k_pre(const float* __restrict__ params, const float* __restrict__ head_w) {
    int t = threadIdx.x;  // 256
    if (t < 48) {
        int d = t >> 4, w = t & 15;
        float th = params[(d * 16 + w) * 2 + 0] * 0.5f;
        g_cs[d][w] = make_float2(cosf(th), sinf(th));
    }
    for (int d = 0; d < 3; d++) {
        float ah = 0.f, al = 0.f;
        for (int w = 0; w < 8; w++) {
            float ph = params[(d * 16 + w) * 2 + 1] * 0.5f;
            ah += ((t >> (7 - w)) & 1) ? -ph : ph;
        }
        for (int w = 8; w < 16; w++) {
            float ph = params[(d * 16 + w) * 2 + 1] * 0.5f;
            al += ((t >> (15 - w)) & 1) ? -ph : ph;
        }
        g_Dhi[d][t] = make_float2(cosf(ah), -sinf(ah));
        g_Dlo[d][t] = make_float2(cosf(al), -sinf(al));
    }
    float gh = 0.f, gl = 0.f;
    for (int w = 0; w < 8; w++)  gh += ((t >> (7 - w)) & 1)  ? -head_w[w] : head_w[w];
    for (int w = 8; w < 16; w++) gl += ((t >> (15 - w)) & 1) ? -head_w[w] : head_w[w];
    g_Ghi[t] = gh;
    g_Glo[t] = gl;
}

// ---- K1: layer-0 real RY on wires 4..15 (bits 11..0), contiguous tile ----
__global__ void __launch_bounds__(256) k_low_real(const float* __restrict__ in) {
    __shared__ float tile[4096];
    float* out = (float*)(void*)g_bufA;
    int base = blockIdx.x << 12;
    int t = threadIdx.x;
    float v[16];
#pragma unroll
    for (int j = 0; j < 16; j++) v[j] = in[base + t + (j << 8)];
    bfly4_real(v, 0, 7);                       // bits 8..11 -> wires 7..4
#pragma unroll
    for (int j = 0; j < 16; j++) tile[swz(t | (j << 8))] = v[j];
    __syncthreads();
    {
        int b = (t & 15) | ((t >> 4) << 8);
#pragma unroll
        for (int j = 0; j < 16; j++) v[j] = tile[swz(b | (j << 4))];
        bfly4_real(v, 0, 11);                  // bits 4..7 -> wires 11..8
#pragma unroll
        for (int j = 0; j < 16; j++) tile[swz(b | (j << 4))] = v[j];
    }
    __syncthreads();
    {
        int b = t << 4;
#pragma unroll
        for (int j = 0; j < 16; j++) v[j] = tile[swz(b | j)];
        bfly4_real(v, 0, 15);                  // bits 0..3 -> wires 15..12
        float4* o = (float4*)(out + base + b);
#pragma unroll
        for (int m = 0; m < 4; m++)
            o[m] = make_float4(v[4 * m], v[4 * m + 1], v[4 * m + 2], v[4 * m + 3]);
    }
}

// ---- K2 (k_fuse0): L0 wires 0..3 (real) + D0 + P0 scatter + L1 wires 8..15 in-tile.
//      bufA(real) -> bufB(complex).
//      Staged tile index u = (dest[15:12]<<8)|dest[7:0]; dest[11:8] row-implicit. ----
__global__ void __launch_bounds__(256) k_fuse0() {
    __shared__ u64 st[4096];
    const float* in = (const float*)(const void*)g_bufA;
    u64* out = (u64*)(void*)g_bufB;
    int s = blockIdx.x >> 4, mid = blockIdx.x & 15;
    int lo = threadIdx.x;
    int sbase = s << 16;
    int abase = (mid << 8) | lo;
    float v[16];
#pragma unroll
    for (int h = 0; h < 16; h++) v[h] = in[sbase | (h << 12) | abase];
    bfly4_real(v, 0, 3);                       // bits 12..15 -> wires 3..0
    float2 dlo = g_Dlo[0][lo];
#pragma unroll
    for (int h = 0; h < 16; h++) {
        int a = (h << 12) | abase;
        int dest = permM(a);
        float2 dh = g_Dhi[0][(a >> 8) & 255];
        float dcr = dh.x * dlo.x - dh.y * dlo.y;
        float dci = dh.x * dlo.y + dh.y * dlo.x;
        st[sw2(((dest >> 12) << 8) | (dest & 255))] = mul2(pk(v[h], v[h]), pk(dcr, dci));
    }
    __syncthreads();
    // stage S: L1 wires 8..11 (dest bits 7..4); thread = (row k, m)
    {
        int k = threadIdx.x >> 4, m = threadIdx.x & 15;
        u64 w[16];
#pragma unroll
        for (int j = 0; j < 16; j++) w[j] = st[sw2((k << 8) | (j << 4) | m)];
        bfly4_pk(w, 1, 11);
#pragma unroll
        for (int j = 0; j < 16; j++) st[sw2((k << 8) | (j << 4) | m)] = w[j];
    }
    __syncthreads();
    // stage T: L1 wires 12..15 (dest bits 3..0); thread = (row k, gg); ends in regs,
    // written straight to gmem as contiguous 128B runs (coalesced 2KB rows).
    {
        int k = threadIdx.x >> 4, gg = threadIdx.x & 15;
        u64 w[16];
#pragma unroll
        for (int j = 0; j < 16; j++) w[j] = st[sw2((k << 8) | (gg << 4) | j)];
        bfly4_pk(w, 1, 15);
        int ms = sfx4(mid);
        int H = (k << 4) | (ms ^ ((k & 1) ? 15 : 0));      // dest bits 8..15
        ulonglong2* o = (ulonglong2*)(out + (sbase | (H << 8) | (gg << 4)));
#pragma unroll
        for (int m2 = 0; m2 < 8; m2++) {
            ulonglong2 p; p.x = w[2 * m2]; p.y = w[2 * m2 + 1];
            o[m2] = p;
        }
    }
}

// ---- K3 (k_mid4): L1 wires 4..7 (bits 11..8), pure-register, in-place on bufB ----
__global__ void __launch_bounds__(256) k_mid4() {
    u64* buf = (u64*)(void*)g_bufB;
    int base = blockIdx.x << 12;
    int t = threadIdx.x;
    u64 v[16];
#pragma unroll
    for (int j = 0; j < 16; j++) v[j] = buf[base + t + (j << 8)];
    bfly4_pk(v, 1, 7);                         // bits 8..11 -> wires 7..4
#pragma unroll
    for (int j = 0; j < 16; j++) buf[base + t + (j << 8)] = v[j];
}

// ---- K4 (k_fuse1): L1 wires 0..3 + D1 + P1 scatter + L2 wires 8..15 in-tile.
//      bufB -> bufA. ----
__global__ void __launch_bounds__(256) k_fuse1() {
    __shared__ u64 st[4096];
    const u64* in = (const u64*)(const void*)g_bufB;
    u64* out = (u64*)(void*)g_bufA;
    int s = blockIdx.x >> 4, mid = blockIdx.x & 15;
    int lo = threadIdx.x;
    int sbase = s << 16;
    int abase = (mid << 8) | lo;
    u64 v[16];
#pragma unroll
    for (int h = 0; h < 16; h++) v[h] = in[sbase | (h << 12) | abase];
    bfly4_pk(v, 1, 3);                         // L1 wires 3..0
    float2 dlo = g_Dlo[1][lo];
#pragma unroll
    for (int h = 0; h < 16; h++) {
        int a = (h << 12) | abase;
        int dest = permM(a);
        float2 dh = g_Dhi[1][(a >> 8) & 255];
        float dcr = dh.x * dlo.x - dh.y * dlo.y;
        float dci = dh.x * dlo.y + dh.y * dlo.x;
        float xr, xi; upk(v[h], xr, xi);
        u64 res = fma2(pk(xi, xi), pk(-dci, dcr), mul2(pk(xr, xr), pk(dcr, dci)));
        st[sw2(((dest >> 12) << 8) | (dest & 255))] = res;
    }
    __syncthreads();
    {
        int k = threadIdx.x >> 4, m = threadIdx.x & 15;
        u64 w[16];
#pragma unroll
        for (int j = 0; j < 16; j++) w[j] = st[sw2((k << 8) | (j << 4) | m)];
        bfly4_pk(w, 2, 11);                    // L2 wires 8..11
#pragma unroll
        for (int j = 0; j < 16; j++) st[sw2((k << 8) | (j << 4) | m)] = w[j];
    }
    __syncthreads();
    {
        int k = threadIdx.x >> 4, gg = threadIdx.x & 15;
        u64 w[16];
#pragma unroll
        for (int j = 0; j < 16; j++) w[j] = st[sw2((k << 8) | (gg << 4) | j)];
        bfly4_pk(w, 2, 15);                    // L2 wires 12..15
        int ms = sfx4(mid);
        int H = (k << 4) | (ms ^ ((k & 1) ? 15 : 0));
        ulonglong2* o = (ulonglong2*)(out + (sbase | (H << 8) | (gg << 4)));
#pragma unroll
        for (int m2 = 0; m2 < 8; m2++) {
            ulonglong2 p; p.x = w[2 * m2]; p.y = w[2 * m2 + 1];
            o[m2] = p;
        }
    }
}

// ---- K5 (k_tail): L2 wires 4..7 (bits 11..8) + wires 0..3 (bits 15..12) +
//      fused measurement (D2 skipped; P2 folded into sign lookup). bufA -> partials.
//      Tile: bits 8..15 full x 16 lo values; smem 32KB; ends in regs -> reduce. ----
__global__ void __launch_bounds__(256) k_tail() {
    __shared__ u64 st[4096];
    const u64* in = (const u64*)(const void*)g_bufA;
    int s = blockIdx.x >> 4, lch = blockIdx.x & 15;
    int loBase = lch << 4;
    int sbase = s << 16;
    int t = threadIdx.x;
    // load: thread (Hlo4 = t>>4 initial offset, l = t&15); iterate HH in steps of 16
    {
        int l = t & 15, Ho = t >> 4;
        u64 w[16];
#pragma unroll
        for (int i = 0; i < 16; i++) {
            int HH = Ho + (i << 4);
            w[i] = in[sbase | (HH << 8) | (loBase + l)];
        }
#pragma unroll
        for (int i = 0; i < 16; i++) {
            int HH = Ho + (i << 4);
            st[(HH << 4) | l] = w[i];
        }
    }
    __syncthreads();
    // stage A: wires 4..7 (HH bits 0..3 = global bits 8..11); thread = (Hhi, l)
    {
        int Hhi = t >> 4, l = t & 15;
        u64 w[16];
#pragma unroll
        for (int j = 0; j < 16; j++) w[j] = st[(Hhi << 8) | (j << 4) | l];
        bfly4_pk(w, 2, 7);
#pragma unroll
        for (int j = 0; j < 16; j++) st[(Hhi << 8) | (j << 4) | l] = w[j];
    }
    __syncthreads();
    // stage B: wires 0..3 (HH bits 4..7 = global bits 12..15); thread = (Hlo, l);
    // measurement directly from registers.
    float acc = 0.f;
    {
        int Hlo = t >> 4, l = t & 15;
        u64 w[16];
#pragma unroll
        for (int j = 0; j < 16; j++) w[j] = st[(j << 8) | (Hlo << 4) | l];
        bfly4_pk(w, 2, 3);
        u64 accP = pk(0.f, 0.f);
#pragma unroll
        for (int j = 0; j < 16; j++) {
            int HH = (j << 4) | Hlo;
            int y = permM((HH << 8) | (loBase + l));
            float g = g_Ghi[(y >> 8) & 255] + g_Glo[y & 255];
            accP = fma2(w[j], mul2(w[j], pk(g, g)), accP);
        }
        float ar, ai; upk(accP, ar, ai);
        acc = ar + ai;
    }
#pragma unroll
    for (int o = 16; o; o >>= 1) acc += __shfl_xor_sync(0xFFFFFFFFu, acc, o);
    __shared__ float red[8];
    if ((t & 31) == 0) red[t >> 5] = acc;
    __syncthreads();
    if (t == 0) {
        float tt = 0.f;
#pragma unroll
        for (int i = 0; i < 8; i++) tt += red[i];
        g_partials[blockIdx.x] = tt;
    }
}

__global__ void k_final(const float* __restrict__ head_b, float* __restrict__ out) {
    int s = threadIdx.x;  // 128
    float a = 0.f;
#pragma unroll
    for (int m = 0; m < 16; m++) a += g_partials[(s << 4) + m];
    out[s] = head_b[0] + a;
}

extern "C" void kernel_launch(void* const* d_in, const int* in_sizes, int n_in,
                              void* d_out, int out_size) {
    const float* state  = (const float*)d_in[0];  // (128, 65536)
    const float* params = (const float*)d_in[1];  // (3, 16, 2)
    const float* head_w = (const float*)d_in[2];  // (1, 16)
    const float* head_b = (const float*)d_in[3];  // (1,)
    float* out = (float*)d_out;                   // (128,)
    (void)in_sizes; (void)n_in; (void)out_size;

    k_pre<<<1, 256>>>(params, head_w);
    k_low_real<<<2048, 256>>>(state);   // L0 wires 4..15           (state -> bufA real)
    k_fuse0<<<2048, 256>>>();           // L0 w0..3 +D0+P0+ L1 w8..15 (bufA -> bufB)
    k_mid4<<<2048, 256>>>();            // L1 wires 4..7, pure-reg   (bufB in-place)
    k_fuse1<<<2048, 256>>>();           // L1 w0..3 +D1+P1+ L2 w8..15 (bufB -> bufA)
    k_tail<<<2048, 256>>>();            // L2 w4..7 + w0..3 + measure (bufA -> partials)
    k_final<<<1, 128>>>(head_b, out);
}

// round 8
// speedup vs baseline: 1.5538x; 1.5538x over previous
#include <cuda_runtime.h>

#define BATCH 128
#define DIM   65536
#define NELEM (BATCH * DIM)

typedef unsigned long long u64;

// ---- scratch / precomputed tables (static device memory; no runtime allocs) ----
static __device__ float2 g_bufA[NELEM];          // 64 MB
static __device__ float2 g_bufB[NELEM];          // 64 MB
static __device__ float  g_partials[BATCH * 16];
static __device__ float2 g_cs[3][16];            // (cos(th/2), sin(th/2)) per layer/wire
static __device__ float2 g_Dhi[3][256];          // diagonal phase, wires 0..7  (bits 15..8)
static __device__ float2 g_Dlo[3][256];          // diagonal phase, wires 8..15 (bits 7..0)
static __device__ float  g_Ghi[256];             // head-weighted Z signs, wires 0..7
static __device__ float  g_Glo[256];             // head-weighted Z signs, wires 8..15

// ---- packed f32x2 helpers (FFMA2 path: PTX-only) ----
__device__ __forceinline__ u64 pk(float x, float y) {
    u64 r; asm("mov.b64 %0,{%1,%2};" : "=l"(r) : "f"(x), "f"(y)); return r;
}
__device__ __forceinline__ void upk(u64 a, float& x, float& y) {
    asm("mov.b64 {%0,%1},%2;" : "=f"(x), "=f"(y) : "l"(a));
}
__device__ __forceinline__ u64 fma2(u64 a, u64 b, u64 c) {
    u64 r; asm("fma.rn.f32x2 %0,%1,%2,%3;" : "=l"(r) : "l"(a), "l"(b), "l"(c)); return r;
}
__device__ __forceinline__ u64 mul2(u64 a, u64 b) {
    u64 r; asm("mul.rn.f32x2 %0,%1,%2;" : "=l"(r) : "l"(a), "l"(b)); return r;
}

// swizzles
__device__ __forceinline__ int swz(int i) {      // for k_low_real patterns
    return i ^ ((i >> 4) & 15) ^ (((i >> 8) & 1) << 4);
}
__device__ __forceinline__ int sw2(int i) {      // for fuse-kernel staged tile
    return i ^ ((i >> 4) & 15);
}

// Composite CNOT-ring permutation (forward basis map): out[M(a)] = psi[a].
__device__ __forceinline__ int permM(int a) {
    int t = a;
    t ^= t >> 8; t ^= t >> 4; t ^= t >> 2; t ^= t >> 1;
    return t ^ ((t & 1) << 15);
}
__device__ __forceinline__ int sfx4(int m) { m ^= m >> 2; m ^= m >> 1; return m & 15; }

// 4 RY butterflies; local bit q of j <-> wire (wtop - q).
__device__ __forceinline__ void bfly4_real(float v[16], int layer, int wtop) {
#pragma unroll
    for (int q = 0; q < 4; q++) {
        float2 cs = g_cs[layer][wtop - q];
        float c = cs.x, s = cs.y;
#pragma unroll
        for (int j = 0; j < 16; j++) {
            if (!(j & (1 << q))) {
                int j1 = j | (1 << q);
                float x0 = v[j], x1 = v[j1];
                v[j]  = c * x0 - s * x1;
                v[j1] = s * x0 + c * x1;
            }
        }
    }
}

__device__ __forceinline__ void bfly4_pk(u64 v[16], int layer, int wtop) {
#pragma unroll
    for (int q = 0; q < 4; q++) {
        float2 cs = g_cs[layer][wtop - q];
        u64 cc = pk(cs.x, cs.x), sp = pk(cs.y, cs.y), sn = pk(-cs.y, -cs.y);
#pragma unroll
        for (int j = 0; j < 16; j++) {
            if (!(j & (1 << q))) {
                int j1 = j | (1 << q);
                u64 x0 = v[j], x1 = v[j1];
                v[j]  = fma2(sn, x1, mul2(cc, x0));
                v[j1] = fma2(sp, x0, mul2(cc, x1));
            }
        }
    }
}

// ---- precompute tables ----
__global__ void k_pre(const float* __restrict__ params, const float* __restrict__ head_w) {
    int t = threadIdx.x;  // 256
    if (t < 48) {
        int d = t >> 4, w = t & 15;
        float th = params[(d * 16 + w) * 2 + 0] * 0.5f;
        g_cs[d][w] = make_float2(cosf(th), sinf(th));
    }
    for (int d = 0; d < 3; d++) {
        float ah = 0.f, al = 0.f;
        for (int w = 0; w < 8; w++) {
            float ph = params[(d * 16 + w) * 2 + 1] * 0.5f;
            ah += ((t >> (7 - w)) & 1) ? -ph : ph;
        }
        for (int w = 8; w < 16; w++) {
            float ph = params[(d * 16 + w) * 2 + 1] * 0.5f;
            al += ((t >> (15 - w)) & 1) ? -ph : ph;
        }
        g_Dhi[d][t] = make_float2(cosf(ah), -sinf(ah));
        g_Dlo[d][t] = make_float2(cosf(al), -sinf(al));
    }
    float gh = 0.f, gl = 0.f;
    for (int w = 0; w < 8; w++)  gh += ((t >> (7 - w)) & 1)  ? -head_w[w] : head_w[w];
    for (int w = 8; w < 16; w++) gl += ((t >> (15 - w)) & 1) ? -head_w[w] : head_w[w];
    g_Ghi[t] = gh;
    g_Glo[t] = gl;
}

// ---- K1: layer-0 real RY on wires 4..15 (bits 11..0), contiguous tile ----
__global__ void __launch_bounds__(256) k_low_real(const float* __restrict__ in) {
    __shared__ float tile[4096];
    float* out = (float*)(void*)g_bufA;
    int base = blockIdx.x << 12;
    int t = threadIdx.x;
    float v[16];
#pragma unroll
    for (int j = 0; j < 16; j++) v[j] = in[base + t + (j << 8)];
    bfly4_real(v, 0, 7);                       // bits 8..11 -> wires 7..4
#pragma unroll
    for (int j = 0; j < 16; j++) tile[swz(t | (j << 8))] = v[j];
    __syncthreads();
    {
        int b = (t & 15) | ((t >> 4) << 8);
#pragma unroll
        for (int j = 0; j < 16; j++) v[j] = tile[swz(b | (j << 4))];
        bfly4_real(v, 0, 11);                  // bits 4..7 -> wires 11..8
#pragma unroll
        for (int j = 0; j < 16; j++) tile[swz(b | (j << 4))] = v[j];
    }
    __syncthreads();
    {
        int b = t << 4;
#pragma unroll
        for (int j = 0; j < 16; j++) v[j] = tile[swz(b | j)];
        bfly4_real(v, 0, 15);                  // bits 0..3 -> wires 15..12
        float4* o = (float4*)(out + base + b);
#pragma unroll
        for (int m = 0; m < 4; m++)
            o[m] = make_float4(v[4 * m], v[4 * m + 1], v[4 * m + 2], v[4 * m + 3]);
    }
}

// ---- K2 (k_fuse0): L0 wires 0..3 (real) + D0 + P0 scatter + L1 wires 8..15 in-tile.
//      bufA(real) -> bufB(complex). g_Dhi values are block-uniform -> staged in smem. ----
__global__ void __launch_bounds__(256) k_fuse0() {
    __shared__ u64 st[4096];
    __shared__ float2 sDh[16];
    const float* in = (const float*)(const void*)g_bufA;
    u64* out = (u64*)(void*)g_bufB;
    int s = blockIdx.x >> 4, mid = blockIdx.x & 15;
    int lo = threadIdx.x;
    int sbase = s << 16;
    int abase = (mid << 8) | lo;
    if (lo < 16) sDh[lo] = g_Dhi[0][(lo << 4) | mid];   // dh for h = lo
    float v[16];
#pragma unroll
    for (int h = 0; h < 16; h++) v[h] = in[sbase | (h << 12) | abase];
    bfly4_real(v, 0, 3);                       // bits 12..15 -> wires 3..0
    float2 dlo = g_Dlo[0][lo];
    __syncthreads();                           // sDh visible; st untouched yet
#pragma unroll
    for (int h = 0; h < 16; h++) {
        int a = (h << 12) | abase;
        int dest = permM(a);
        float2 dh = sDh[h];
        float dcr = dh.x * dlo.x - dh.y * dlo.y;
        float dci = dh.x * dlo.y + dh.y * dlo.x;
        st[sw2(((dest >> 12) << 8) | (dest & 255))] = mul2(pk(v[h], v[h]), pk(dcr, dci));
    }
    __syncthreads();
    // stage S: L1 wires 8..11 (dest bits 7..4); thread = (row k, m)
    {
        int k = threadIdx.x >> 4, m = threadIdx.x & 15;
        u64 w[16];
#pragma unroll
        for (int j = 0; j < 16; j++) w[j] = st[sw2((k << 8) | (j << 4) | m)];
        bfly4_pk(w, 1, 11);
#pragma unroll
        for (int j = 0; j < 16; j++) st[sw2((k << 8) | (j << 4) | m)] = w[j];
    }
    __syncthreads();
    // stage T: L1 wires 12..15 (dest bits 3..0); ends in regs -> coalesced 2KB rows.
    {
        int k = threadIdx.x >> 4, gg = threadIdx.x & 15;
        u64 w[16];
#pragma unroll
        for (int j = 0; j < 16; j++) w[j] = st[sw2((k << 8) | (gg << 4) | j)];
        bfly4_pk(w, 1, 15);
        int ms = sfx4(mid);
        int H = (k << 4) | (ms ^ ((k & 1) ? 15 : 0));      // dest bits 8..15
        ulonglong2* o = (ulonglong2*)(out + (sbase | (H << 8) | (gg << 4)));
#pragma unroll
        for (int m2 = 0; m2 < 8; m2++) {
            ulonglong2 p; p.x = w[2 * m2]; p.y = w[2 * m2 + 1];
            o[m2] = p;
        }
    }
}

// ---- K3 (k_mid4): L1 wires 4..7 (bits 11..8), pure-register, in-place on bufB ----
__global__ void __launch_bounds__(256, 5) k_mid4() {
    u64* buf = (u64*)(void*)g_bufB;
    int base = blockIdx.x << 12;
    int t = threadIdx.x;
    u64 v[16];
#pragma unroll
    for (int j = 0; j < 16; j++) v[j] = buf[base + t + (j << 8)];
    bfly4_pk(v, 1, 7);                         // bits 8..11 -> wires 7..4
#pragma unroll
    for (int j = 0; j < 16; j++) buf[base + t + (j << 8)] = v[j];
}

// ---- K4 (k_fuse1): L1 wires 0..3 + D1 + P1 scatter + L2 wires 8..15 in-tile.
//      bufB -> bufA. ----
__global__ void __launch_bounds__(256) k_fuse1() {
    __shared__ u64 st[4096];
    __shared__ float2 sDh[16];
    const u64* in = (const u64*)(const void*)g_bufB;
    u64* out = (u64*)(void*)g_bufA;
    int s = blockIdx.x >> 4, mid = blockIdx.x & 15;
    int lo = threadIdx.x;
    int sbase = s << 16;
    int abase = (mid << 8) | lo;
    if (lo < 16) sDh[lo] = g_Dhi[1][(lo << 4) | mid];
    u64 v[16];
#pragma unroll
    for (int h = 0; h < 16; h++) v[h] = in[sbase | (h << 12) | abase];
    bfly4_pk(v, 1, 3);                         // L1 wires 3..0
    float2 dlo = g_Dlo[1][lo];
    __syncthreads();
#pragma unroll
    for (int h = 0; h < 16; h++) {
        int a = (h << 12) | abase;
        int dest = permM(a);
        float2 dh = sDh[h];
        float dcr = dh.x * dlo.x - dh.y * dlo.y;
        float dci = dh.x * dlo.y + dh.y * dlo.x;
        float xr, xi; upk(v[h], xr, xi);
        u64 res = fma2(pk(xi, xi), pk(-dci, dcr), mul2(pk(xr, xr), pk(dcr, dci)));
        st[sw2(((dest >> 12) << 8) | (dest & 255))] = res;
    }
    __syncthreads();
    {
        int k = threadIdx.x >> 4, m = threadIdx.x & 15;
        u64 w[16];
#pragma unroll
        for (int j = 0; j < 16; j++) w[j] = st[sw2((k << 8) | (j << 4) | m)];
        bfly4_pk(w, 2, 11);                    // L2 wires 8..11
#pragma unroll
        for (int j = 0; j < 16; j++) st[sw2((k << 8) | (j << 4) | m)] = w[j];
    }
    __syncthreads();
    {
        int k = threadIdx.x >> 4, gg = threadIdx.x & 15;
        u64 w[16];
#pragma unroll
        for (int j = 0; j < 16; j++) w[j] = st[sw2((k << 8) | (gg << 4) | j)];
        bfly4_pk(w, 2, 15);                    // L2 wires 12..15
        int ms = sfx4(mid);
        int H = (k << 4) | (ms ^ ((k & 1) ? 15 : 0));
        ulonglong2* o = (ulonglong2*)(out + (sbase | (H << 8) | (gg << 4)));
#pragma unroll
        for (int m2 = 0; m2 < 8; m2++) {
            ulonglong2 p; p.x = w[2 * m2]; p.y = w[2 * m2 + 1];
            o[m2] = p;
        }
    }
}

// ---- K5 (k_tail): L2 wires 4..7 + wires 0..3 + fused measurement
//      (D2 skipped; P2 folded into sign lookup). bufA -> partials.
//      Sign tables staged in smem to avoid 16-deep gmem gather hoisting. ----
__global__ void __launch_bounds__(256) k_tail() {
    __shared__ u64 st[4096];
    __shared__ float sGhi[256], sGlo[256];
    const u64* in = (const u64*)(const void*)g_bufA;
    int s = blockIdx.x >> 4, lch = blockIdx.x & 15;
    int loBase = lch << 4;
    int sbase = s << 16;
    int t = threadIdx.x;
    sGhi[t] = g_Ghi[t];
    sGlo[t] = g_Glo[t];
    // load tile: bits 8..15 full x 16 lo values
    {
        int l = t & 15, Ho = t >> 4;
#pragma unroll
        for (int i = 0; i < 16; i++) {
            int HH = Ho + (i << 4);
            st[(HH << 4) | l] = in[sbase | (HH << 8) | (loBase + l)];
        }
    }
    __syncthreads();
    // stage A: wires 4..7 (HH bits 0..3 = global bits 8..11)
    {
        int Hhi = t >> 4, l = t & 15;
        u64 w[16];
#pragma unroll
        for (int j = 0; j < 16; j++) w[j] = st[(Hhi << 8) | (j << 4) | l];
        bfly4_pk(w, 2, 7);
#pragma unroll
        for (int j = 0; j < 16; j++) st[(Hhi << 8) | (j << 4) | l] = w[j];
    }
    __syncthreads();
    // stage B: wires 0..3 (HH bits 4..7 = global bits 12..15) + measurement
    float acc = 0.f;
    {
        int Hlo = t >> 4, l = t & 15;
        u64 w[16];
#pragma unroll
        for (int j = 0; j < 16; j++) w[j] = st[(j << 8) | (Hlo << 4) | l];
        bfly4_pk(w, 2, 3);
        u64 accP = pk(0.f, 0.f);
#pragma unroll
        for (int j = 0; j < 16; j++) {
            int HH = (j << 4) | Hlo;
            int y = permM((HH << 8) | (loBase + l));
            float g = sGhi[(y >> 8) & 255] + sGlo[y & 255];
            accP = fma2(w[j], mul2(w[j], pk(g, g)), accP);
        }
        float ar, ai; upk(accP, ar, ai);
        acc = ar + ai;
    }
#pragma unroll
    for (int o = 16; o; o >>= 1) acc += __shfl_xor_sync(0xFFFFFFFFu, acc, o);
    __shared__ float red[8];
    if ((t & 31) == 0) red[t >> 5] = acc;
    __syncthreads();
    if (t == 0) {
        float tt = 0.f;
#pragma unroll
        for (int i = 0; i < 8; i++) tt += red[i];
        g_partials[blockIdx.x] = tt;
    }
}

__global__ void k_final(const float* __restrict__ head_b, float* __restrict__ out) {
    int s = threadIdx.x;  // 128
    float a = 0.f;
#pragma unroll
    for (int m = 0; m < 16; m++) a += g_partials[(s << 4) + m];
    out[s] = head_b[0] + a;
}

extern "C" void kernel_launch(void* const* d_in, const int* in_sizes, int n_in,
                              void* d_out, int out_size) {
    const float* state  = (const float*)d_in[0];  // (128, 65536)
    const float* params = (const float*)d_in[1];  // (3, 16, 2)
    const float* head_w = (const float*)d_in[2];  // (1, 16)
    const float* head_b = (const float*)d_in[3];  // (1,)
    float* out = (float*)d_out;                   // (128,)
    (void)in_sizes; (void)n_in; (void)out_size;

    k_pre<<<1, 256>>>(params, head_w);
    k_low_real<<<2048, 256>>>(state);   // L0 wires 4..15            (state -> bufA real)
    k_fuse0<<<2048, 256>>>();           // L0 w0..3 +D0+P0+ L1 w8..15 (bufA -> bufB)
    k_mid4<<<2048, 256>>>();            // L1 wires 4..7, pure-reg    (bufB in-place)
    k_fuse1<<<2048, 256>>>();           // L1 w0..3 +D1+P1+ L2 w8..15 (bufB -> bufA)
    k_tail<<<2048, 256>>>();            // L2 w4..7 + w0..3 + measure (bufA -> partials)
    k_final<<<1, 128>>>(head_b, out);
}